// round 13
// baseline (speedup 1.0000x reference)
#include <cuda_runtime.h>
#include <cuda_bf16.h>

#define HID 4096
#define MH 16384             // 4 * HIDDEN
#define TOK 2
#define NT 256
#define NWARP (NT / 32)      // 8
#define NACC (TOK * 5)       // 10
#define NK (MH / 4 / NT)     // 16 float4-iterations per token
#define F4H (HID / 4)        // 1024

__device__ unsigned g_tile_ctr;

__device__ __forceinline__ float bflo(unsigned u) {   // low bf16 -> f32
    return __uint_as_float(u << 16);
}
__device__ __forceinline__ float bfhi(unsigned u) {   // high bf16 -> f32
    return __uint_as_float(u & 0xFFFF0000u);
}
// round fp32 pair -> packed bf16x2 (RN, matches astype(bfloat16))
__device__ __forceinline__ unsigned pack_bf2(float a, float b) {
    __nv_bfloat162 p = __floats2bfloat162_rn(a, b);
    return *reinterpret_cast<unsigned*>(&p);
}

// phase-2 chunk c (0..7) of tile with base token ptok0: token t=c>>2, group g=c&3.
__device__ __forceinline__ void phase2_chunk(
    const float4* __restrict__ x4, float* __restrict__ out,
    size_t ptok0, int c, int tid, const float* __restrict__ w)
{
    const int t  = c >> 2;
    const int g  = c & 3;
    const int h4 = tid + g * NT;
    const float4* xp = x4 + (ptok0 + t) * (MH / 4);
    float4 a = __ldcs(xp + 0 * F4H + h4);
    float4 b = __ldcs(xp + 1 * F4H + h4);
    float4 cc = __ldcs(xp + 2 * F4H + h4);
    float4 d = __ldcs(xp + 3 * F4H + h4);
    const float w0 = w[t * 4 + 0], w1 = w[t * 4 + 1];
    const float w2 = w[t * 4 + 2], w3 = w[t * 4 + 3];

    unsigned qa0 = pack_bf2(a.x, a.y),  qa1 = pack_bf2(a.z, a.w);
    unsigned qb0 = pack_bf2(b.x, b.y),  qb1 = pack_bf2(b.z, b.w);
    unsigned qc0 = pack_bf2(cc.x, cc.y), qc1 = pack_bf2(cc.z, cc.w);
    unsigned qd0 = pack_bf2(d.x, d.y),  qd1 = pack_bf2(d.z, d.w);

    float4 r;
    r.x = w0 * bflo(qa0) + w1 * bflo(qb0) + w2 * bflo(qc0) + w3 * bflo(qd0);
    r.y = w0 * bfhi(qa0) + w1 * bfhi(qb0) + w2 * bfhi(qc0) + w3 * bfhi(qd0);
    r.z = w0 * bflo(qa1) + w1 * bflo(qb1) + w2 * bflo(qc1) + w3 * bflo(qd1);
    r.w = w0 * bfhi(qa1) + w1 * bfhi(qb1) + w2 * bfhi(qc1) + w3 * bfhi(qd1);

    __stcs(reinterpret_cast<float4*>(out + (ptok0 + t) * HID) + h4, r);
}

__global__ __launch_bounds__(NT, 4) void hchead_kernel(
    const float* __restrict__ x,
    const float* __restrict__ fn,
    const float* __restrict__ scale,
    const float* __restrict__ base,
    float* __restrict__ out,
    int ntiles)
{
    __shared__ float red[NWARP * NACC];
    __shared__ float wsh[2][TOK * 4];    // double-buffered mixing weights
    __shared__ int   tile_sh;

    const int tid  = threadIdx.x;
    const int warp = tid >> 5, lane = tid & 31;

    const float4* x4  = reinterpret_cast<const float4*>(x);
    const float4* fn4 = reinterpret_cast<const float4*>(fn);

    int prev_tile = -1;
    int par = 0;

    for (;;) {
        if (tid == 0) tile_sh = (int)atomicAdd(&g_tile_ctr, 1u);
        __syncthreads();
        const int tile = tile_sh;
        if (tile >= ntiles) break;

        const size_t tok0  = (size_t)tile * TOK;
        const bool   hp    = (prev_tile >= 0);
        const size_t ptok0 = (size_t)(hp ? prev_tile : 0) * TOK;
        const float* wprev = wsh[par ^ 1];

        float acc[NACC];
#pragma unroll
        for (int i = 0; i < NACC; i++) acc[i] = 0.f;

        // ---- Phase 1 (this tile) + interleaved phase 2 (previous tile) ----
#pragma unroll 4
        for (int k = 0; k < NK; k++) {
            const int f = tid + k * NT;
            const float4 g0 = fn4[0 * (MH / 4) + f];
            const float4 g1 = fn4[1 * (MH / 4) + f];
            const float4 g2 = fn4[2 * (MH / 4) + f];
            const float4 g3 = fn4[3 * (MH / 4) + f];
            float4 v0 = x4[(tok0 + 0) * (MH / 4) + f];
            float4 v1 = x4[(tok0 + 1) * (MH / 4) + f];
#pragma unroll
            for (int t = 0; t < TOK; t++) {
                const float4 v = (t == 0) ? v0 : v1;
                const unsigned p0 = pack_bf2(v.x, v.y);
                const unsigned p1 = pack_bf2(v.z, v.w);
                const float x0 = bflo(p0), x1 = bfhi(p0);
                const float x2 = bflo(p1), x3 = bfhi(p1);
                acc[t * 5 + 0] += x0 * x0 + x1 * x1 + x2 * x2 + x3 * x3;
                acc[t * 5 + 1] += x0 * g0.x + x1 * g0.y + x2 * g0.z + x3 * g0.w;
                acc[t * 5 + 2] += x0 * g1.x + x1 * g1.y + x2 * g1.z + x3 * g1.w;
                acc[t * 5 + 3] += x0 * g2.x + x1 * g2.y + x2 * g2.z + x3 * g2.w;
                acc[t * 5 + 4] += x0 * g3.x + x1 * g3.y + x2 * g3.z + x3 * g3.w;
            }
            // one phase-2 chunk every 2 iterations (8 chunks total)
            if (hp && (k & 1))
                phase2_chunk(x4, out, ptok0, k >> 1, tid, wprev);
        }

        // ---- Block reduction of partials ----
#pragma unroll
        for (int i = 0; i < NACC; i++) {
#pragma unroll
            for (int o = 16; o > 0; o >>= 1)
                acc[i] += __shfl_xor_sync(0xffffffffu, acc[i], o);
        }
        if (lane == 0) {
#pragma unroll
            for (int i = 0; i < NACC; i++) red[warp * NACC + i] = acc[i];
        }
        __syncthreads();

        if (tid < TOK) {
            const int t = tid;
            float ss = 0.f, d0 = 0.f, d1 = 0.f, d2 = 0.f, d3 = 0.f;
#pragma unroll
            for (int w = 0; w < NWARP; w++) {
                ss += red[w * NACC + t * 5 + 0];
                d0 += red[w * NACC + t * 5 + 1];
                d1 += red[w * NACC + t * 5 + 2];
                d2 += red[w * NACC + t * 5 + 3];
                d3 += red[w * NACC + t * 5 + 4];
            }
            const float inv = 1.0f / sqrtf(ss * (1.0f / MH) + 1e-6f);
            const float s = scale[0];
            const float a0 = s * (d0 * inv) + base[0];
            const float a1 = s * (d1 * inv) + base[1];
            const float a2 = s * (d2 * inv) + base[2];
            const float a3 = s * (d3 * inv) + base[3];
            const float idn = 1.0f / (fabsf(a0) + fabsf(a1) + fabsf(a2) + fabsf(a3) + 1e-6f);
            wsh[par][t * 4 + 0] = a0 * idn;
            wsh[par][t * 4 + 1] = a1 * idn;
            wsh[par][t * 4 + 2] = a2 * idn;
            wsh[par][t * 4 + 3] = a3 * idn;
        }
        __syncthreads();

        prev_tile = tile;
        par ^= 1;
    }

    // ---- Drain: phase-2 for the last tile this CTA processed ----
    if (prev_tile >= 0) {
        const size_t ptok0 = (size_t)prev_tile * TOK;
        const float* wprev = wsh[par ^ 1];
#pragma unroll
        for (int c = 0; c < 8; c++)
            phase2_chunk(x4, out, ptok0, c, tid, wprev);
    }
}

extern "C" void kernel_launch(void* const* d_in, const int* in_sizes, int n_in,
                              void* d_out, int out_size) {
    const float* x     = (const float*)d_in[0];   // [T, 4*4096] fp32
    const float* fn    = (const float*)d_in[1];   // [4, 16384]  fp32
    const float* scale = (const float*)d_in[2];   // [1]
    const float* base  = (const float*)d_in[3];   // [4]
    float* out = (float*)d_out;                   // [T, 4096] fp32

    const int T = in_sizes[0] / MH;               // 8192
    const int ntiles = T / TOK;                   // 4096

    // reset the tile ticket counter (async, graph-capturable)
    void* ctr_addr = nullptr;
    cudaGetSymbolAddress(&ctr_addr, g_tile_ctr);
    cudaMemsetAsync(ctr_addr, 0, sizeof(unsigned));

    int nsm = 148;
    cudaDeviceGetAttribute(&nsm, cudaDevAttrMultiProcessorCount, 0);
    int grid = 4 * nsm;
    if (grid > ntiles) grid = ntiles;

    hchead_kernel<<<grid, NT>>>(x, fn, scale, base, out, ntiles);
}

// round 14
// speedup vs baseline: 1.2080x; 1.2080x over previous
#include <cuda_runtime.h>
#include <cuda_bf16.h>

#define HID 4096
#define MH 16384             // 4 * HIDDEN
#define NT 128
#define NWARP (NT / 32)      // 4
#define NACC 5
#define NK (MH / 4 / NT)     // 32 float4-iterations
#define F4H (HID / 4)        // 1024

__device__ __forceinline__ float bflo(unsigned u) {   // low bf16 -> f32
    return __uint_as_float(u << 16);
}
__device__ __forceinline__ float bfhi(unsigned u) {   // high bf16 -> f32
    return __uint_as_float(u & 0xFFFF0000u);
}
// round fp32 pair -> packed bf16x2 (RN, matches astype(bfloat16))
__device__ __forceinline__ unsigned pack_bf2(float a, float b) {
    __nv_bfloat162 p = __floats2bfloat162_rn(a, b);
    return *reinterpret_cast<unsigned*>(&p);
}

__global__ __launch_bounds__(NT, 8) void hchead_kernel(
    const float* __restrict__ x,
    const float* __restrict__ fn,
    const float* __restrict__ scale,
    const float* __restrict__ base,
    float* __restrict__ out)
{
    __shared__ float red[NWARP * NACC];
    __shared__ float wsh[4];

    const int tid  = threadIdx.x;
    const int warp = tid >> 5, lane = tid & 31;
    const size_t tok = (size_t)blockIdx.x;     // one token per CTA

    const float4* x4  = reinterpret_cast<const float4*>(x);
    const float4* fn4 = reinterpret_cast<const float4*>(fn);
    const float4* xp  = x4 + tok * (MH / 4);

    // acc: 0 = sum(x^2), 1+m = dot with fn[m]
    float acc[NACC];
#pragma unroll
    for (int i = 0; i < NACC; i++) acc[i] = 0.f;

    // ------- Phase 1: stream x (DRAM) + fn (L1/L2), accumulate sums -------
#pragma unroll 4
    for (int k = 0; k < NK; k++) {          // 32 iterations
        const int f = tid + k * NT;         // float4 index (j = 4f)
        const float4 g0 = fn4[0 * (MH / 4) + f];
        const float4 g1 = fn4[1 * (MH / 4) + f];
        const float4 g2 = fn4[2 * (MH / 4) + f];
        const float4 g3 = fn4[3 * (MH / 4) + f];
        const float4 v  = xp[f];

        const unsigned p0 = pack_bf2(v.x, v.y);
        const unsigned p1 = pack_bf2(v.z, v.w);
        const float x0 = bflo(p0), x1 = bfhi(p0);
        const float x2 = bflo(p1), x3 = bfhi(p1);
        acc[0] += x0 * x0 + x1 * x1 + x2 * x2 + x3 * x3;
        acc[1] += x0 * g0.x + x1 * g0.y + x2 * g0.z + x3 * g0.w;
        acc[2] += x0 * g1.x + x1 * g1.y + x2 * g1.z + x3 * g1.w;
        acc[3] += x0 * g2.x + x1 * g2.y + x2 * g2.z + x3 * g2.w;
        acc[4] += x0 * g3.x + x1 * g3.y + x2 * g3.z + x3 * g3.w;
    }

    // ------- Block reduction of 5 partials -------
#pragma unroll
    for (int i = 0; i < NACC; i++) {
#pragma unroll
        for (int o = 16; o > 0; o >>= 1)
            acc[i] += __shfl_xor_sync(0xffffffffu, acc[i], o);
    }
    if (lane == 0) {
#pragma unroll
        for (int i = 0; i < NACC; i++) red[warp * NACC + i] = acc[i];
    }
    __syncthreads();

    if (tid == 0) {
        float ss = 0.f, d0 = 0.f, d1 = 0.f, d2 = 0.f, d3 = 0.f;
#pragma unroll
        for (int w = 0; w < NWARP; w++) {
            ss += red[w * NACC + 0];
            d0 += red[w * NACC + 1];
            d1 += red[w * NACC + 2];
            d2 += red[w * NACC + 3];
            d3 += red[w * NACC + 4];
        }
        const float inv = 1.0f / sqrtf(ss * (1.0f / MH) + 1e-6f);
        const float s = scale[0];
        const float a0 = s * (d0 * inv) + base[0];
        const float a1 = s * (d1 * inv) + base[1];
        const float a2 = s * (d2 * inv) + base[2];
        const float a3 = s * (d3 * inv) + base[3];
        const float idn = 1.0f / (fabsf(a0) + fabsf(a1) + fabsf(a2) + fabsf(a3) + 1e-6f);
        wsh[0] = a0 * idn;
        wsh[1] = a1 * idn;
        wsh[2] = a2 * idn;
        wsh[3] = a3 * idn;
    }
    __syncthreads();

    // ------- Phase 2: re-read x (evict-first), re-round, combine, store -------
    // 128 threads, 4096 h -> 8 float4 groups per thread.
    const float w0 = wsh[0], w1 = wsh[1], w2 = wsh[2], w3 = wsh[3];
    float4* op = reinterpret_cast<float4*>(out + tok * HID);
#pragma unroll
    for (int g = 0; g < 8; g++) {
        const int h4 = tid + g * NT;          // float4 idx in hidden dim
        float4 a = __ldcs(xp + 0 * F4H + h4);
        float4 b = __ldcs(xp + 1 * F4H + h4);
        float4 c = __ldcs(xp + 2 * F4H + h4);
        float4 d = __ldcs(xp + 3 * F4H + h4);

        unsigned qa0 = pack_bf2(a.x, a.y), qa1 = pack_bf2(a.z, a.w);
        unsigned qb0 = pack_bf2(b.x, b.y), qb1 = pack_bf2(b.z, b.w);
        unsigned qc0 = pack_bf2(c.x, c.y), qc1 = pack_bf2(c.z, c.w);
        unsigned qd0 = pack_bf2(d.x, d.y), qd1 = pack_bf2(d.z, d.w);

        float4 r;
        r.x = w0 * bflo(qa0) + w1 * bflo(qb0) + w2 * bflo(qc0) + w3 * bflo(qd0);
        r.y = w0 * bfhi(qa0) + w1 * bfhi(qb0) + w2 * bfhi(qc0) + w3 * bfhi(qd0);
        r.z = w0 * bflo(qa1) + w1 * bflo(qb1) + w2 * bflo(qc1) + w3 * bflo(qd1);
        r.w = w0 * bfhi(qa1) + w1 * bfhi(qb1) + w2 * bfhi(qc1) + w3 * bfhi(qd1);

        __stcs(op + h4, r);
    }
}

extern "C" void kernel_launch(void* const* d_in, const int* in_sizes, int n_in,
                              void* d_out, int out_size) {
    const float* x     = (const float*)d_in[0];   // [T, 4*4096] fp32
    const float* fn    = (const float*)d_in[1];   // [4, 16384]  fp32
    const float* scale = (const float*)d_in[2];   // [1]
    const float* base  = (const float*)d_in[3];   // [4]
    float* out = (float*)d_out;                   // [T, 4096] fp32

    const int T = in_sizes[0] / MH;               // 8192
    hchead_kernel<<<T, NT>>>(x, fn, scale, base, out);
}

// round 15
// speedup vs baseline: 1.3089x; 1.0835x over previous
#include <cuda_runtime.h>
#include <cuda_bf16.h>

#define HID 4096
#define MH 16384             // 4 * HIDDEN
#define TOK 2
#define NT 256
#define NWARP (NT / 32)      // 8
#define NACC (TOK * 5)       // 10
#define NK (MH / 4 / NT)     // 16 float4-iterations per token
#define F4H (HID / 4)        // 1024
#define NQ (TOK * 4)         // 8 phase-2 groups (token-major)

__device__ __forceinline__ float bflo(unsigned u) {   // low bf16 -> f32
    return __uint_as_float(u << 16);
}
__device__ __forceinline__ float bfhi(unsigned u) {   // high bf16 -> f32
    return __uint_as_float(u & 0xFFFF0000u);
}
// round fp32 pair -> packed bf16x2 (RN, matches astype(bfloat16))
__device__ __forceinline__ unsigned pack_bf2(float a, float b) {
    __nv_bfloat162 p = __floats2bfloat162_rn(a, b);
    return *reinterpret_cast<unsigned*>(&p);
}

// issue the 4 stream-loads for phase-2 queue item q (t = q>>2, g = q&3)
__device__ __forceinline__ void p2_load(
    const float4* __restrict__ x4, size_t tok0, int q, int tid, float4* buf)
{
    const int t  = q >> 2;
    const int g  = q & 3;
    const int h4 = tid + g * NT;
    const float4* xp = x4 + (tok0 + t) * (MH / 4);
    buf[0] = __ldcs(xp + 0 * F4H + h4);
    buf[1] = __ldcs(xp + 1 * F4H + h4);
    buf[2] = __ldcs(xp + 2 * F4H + h4);
    buf[3] = __ldcs(xp + 3 * F4H + h4);
}

__global__ __launch_bounds__(NT, 4) void hchead_kernel(
    const float* __restrict__ x,
    const float* __restrict__ fn,
    const float* __restrict__ scale,
    const float* __restrict__ base,
    float* __restrict__ out)
{
    __shared__ float red[NWARP * NACC];
    __shared__ float wsh[TOK * 4];

    const int tid  = threadIdx.x;
    const int warp = tid >> 5, lane = tid & 31;
    const size_t tok0 = (size_t)blockIdx.x * TOK;

    const float4* x4  = reinterpret_cast<const float4*>(x);
    const float4* fn4 = reinterpret_cast<const float4*>(fn);

    // acc: t*5+0 = sum(x^2), t*5+1+m = dot with fn[m]
    float acc[NACC];
#pragma unroll
    for (int i = 0; i < NACC; i++) acc[i] = 0.f;

    // ------- Phase 1: stream x (DRAM) + fn (L2), accumulate sums -------
#pragma unroll 4
    for (int k = 0; k < NK; k++) {          // 16 iterations
        const int f = tid + k * NT;         // float4 index (j = 4f)
        const float4 g0 = fn4[0 * (MH / 4) + f];
        const float4 g1 = fn4[1 * (MH / 4) + f];
        const float4 g2 = fn4[2 * (MH / 4) + f];
        const float4 g3 = fn4[3 * (MH / 4) + f];
        float4 v0 = x4[(tok0 + 0) * (MH / 4) + f];
        float4 v1 = x4[(tok0 + 1) * (MH / 4) + f];
#pragma unroll
        for (int t = 0; t < TOK; t++) {
            const float4 v = (t == 0) ? v0 : v1;
            const unsigned p0 = pack_bf2(v.x, v.y);
            const unsigned p1 = pack_bf2(v.z, v.w);
            const float x0 = bflo(p0), x1 = bfhi(p0);
            const float x2 = bflo(p1), x3 = bfhi(p1);
            acc[t * 5 + 0] += x0 * x0 + x1 * x1 + x2 * x2 + x3 * x3;
            acc[t * 5 + 1] += x0 * g0.x + x1 * g0.y + x2 * g0.z + x3 * g0.w;
            acc[t * 5 + 2] += x0 * g1.x + x1 * g1.y + x2 * g1.z + x3 * g1.w;
            acc[t * 5 + 3] += x0 * g2.x + x1 * g2.y + x2 * g2.z + x3 * g2.w;
            acc[t * 5 + 4] += x0 * g3.x + x1 * g3.y + x2 * g3.z + x3 * g3.w;
        }
    }

    // ------- Prefetch phase-2 queue items 0,1 (fly under the reduction) -------
    float4 pf[2][4];
    p2_load(x4, tok0, 0, tid, pf[0]);
    p2_load(x4, tok0, 1, tid, pf[1]);

    // ------- Block reduction of partials -------
#pragma unroll
    for (int i = 0; i < NACC; i++) {
#pragma unroll
        for (int o = 16; o > 0; o >>= 1)
            acc[i] += __shfl_xor_sync(0xffffffffu, acc[i], o);
    }
    if (lane == 0) {
#pragma unroll
        for (int i = 0; i < NACC; i++) red[warp * NACC + i] = acc[i];
    }
    __syncthreads();

    if (tid < TOK) {
        const int t = tid;
        float ss = 0.f, d0 = 0.f, d1 = 0.f, d2 = 0.f, d3 = 0.f;
#pragma unroll
        for (int w = 0; w < NWARP; w++) {
            ss += red[w * NACC + t * 5 + 0];
            d0 += red[w * NACC + t * 5 + 1];
            d1 += red[w * NACC + t * 5 + 2];
            d2 += red[w * NACC + t * 5 + 3];
            d3 += red[w * NACC + t * 5 + 4];
        }
        const float inv = 1.0f / sqrtf(ss * (1.0f / MH) + 1e-6f);
        const float s = scale[0];
        const float a0 = s * (d0 * inv) + base[0];
        const float a1 = s * (d1 * inv) + base[1];
        const float a2 = s * (d2 * inv) + base[2];
        const float a3 = s * (d3 * inv) + base[3];
        const float idn = 1.0f / (fabsf(a0) + fabsf(a1) + fabsf(a2) + fabsf(a3) + 1e-6f);
        wsh[t * 4 + 0] = a0 * idn;
        wsh[t * 4 + 1] = a1 * idn;
        wsh[t * 4 + 2] = a2 * idn;
        wsh[t * 4 + 3] = a3 * idn;
    }
    __syncthreads();

    // ------- Phase 2: pipelined queue, 2 groups of loads always in flight -------
#pragma unroll
    for (int q = 0; q < NQ; q++) {
        const int t = q >> 2;
        const int g = q & 3;
        // consume slot (copy out, then refill with item q+2)
        float4 a = pf[q & 1][0];
        float4 b = pf[q & 1][1];
        float4 c = pf[q & 1][2];
        float4 d = pf[q & 1][3];
        if (q + 2 < NQ)
            p2_load(x4, tok0, q + 2, tid, pf[q & 1]);

        const float w0 = wsh[t * 4 + 0], w1 = wsh[t * 4 + 1];
        const float w2 = wsh[t * 4 + 2], w3 = wsh[t * 4 + 3];

        unsigned qa0 = pack_bf2(a.x, a.y), qa1 = pack_bf2(a.z, a.w);
        unsigned qb0 = pack_bf2(b.x, b.y), qb1 = pack_bf2(b.z, b.w);
        unsigned qc0 = pack_bf2(c.x, c.y), qc1 = pack_bf2(c.z, c.w);
        unsigned qd0 = pack_bf2(d.x, d.y), qd1 = pack_bf2(d.z, d.w);

        float4 r;
        r.x = w0 * bflo(qa0) + w1 * bflo(qb0) + w2 * bflo(qc0) + w3 * bflo(qd0);
        r.y = w0 * bfhi(qa0) + w1 * bfhi(qb0) + w2 * bfhi(qc0) + w3 * bfhi(qd0);
        r.z = w0 * bflo(qa1) + w1 * bflo(qb1) + w2 * bflo(qc1) + w3 * bflo(qd1);
        r.w = w0 * bfhi(qa1) + w1 * bfhi(qb1) + w2 * bfhi(qc1) + w3 * bfhi(qd1);

        const int h4 = tid + g * NT;
        __stcs(reinterpret_cast<float4*>(out + (tok0 + t) * HID) + h4, r);
    }
}

extern "C" void kernel_launch(void* const* d_in, const int* in_sizes, int n_in,
                              void* d_out, int out_size) {
    const float* x     = (const float*)d_in[0];   // [T, 4*4096] fp32
    const float* fn    = (const float*)d_in[1];   // [4, 16384]  fp32
    const float* scale = (const float*)d_in[2];   // [1]
    const float* base  = (const float*)d_in[3];   // [4]
    float* out = (float*)d_out;                   // [T, 4096] fp32

    const int T = in_sizes[0] / MH;               // 8192
    hchead_kernel<<<T / TOK, NT>>>(x, fn, scale, base, out);
}